// round 1
// baseline (speedup 1.0000x reference)
#include <cuda_runtime.h>

// Jacobi 5-iteration temporally-blocked stencil, sm_103a.
// B=16, H=W=1024, cross stencil radius 2, boundary ring (width 2) frozen.

constexpr int HH  = 1024;
constexpr int WW  = 1024;
constexpr int NB  = 16;
constexpr int NIT = 5;
constexpr int T   = 64;             // output tile
constexpr int RAD = 2 * NIT;        // 10 halo
constexpr int L   = T + 2 * RAD;    // 84 local g extent
constexpr int LP  = L + 1;          // 85 padded stride (odd -> conflict free)
constexpr int LR  = T + 2 * (NIT - 1) * 2 - 0; // rhs extent = T+16 = 80
constexpr int LRP = LR + 1;         // 81
constexpr int SMEM_BYTES = (2 * L * LP + LR * LRP) * 4;  // 83,040 B

__global__ void __launch_bounds__(256, 2)
jacobi5_fused(const float* __restrict__ g0,
              const float* __restrict__ rhs,
              const float* __restrict__ dx,
              float* __restrict__ out)
{
    extern __shared__ float sm[];
    float* A  = sm;                 // g buffer 0: L x LP
    float* Bf = sm + L * LP;        // g buffer 1: L x LP
    float* R  = sm + 2 * L * LP;    // rhs: LR x LRP

    const int b  = blockIdx.z;
    const int ti = blockIdx.y * T;  // global row of tile origin
    const int tj = blockIdx.x * T;  // global col of tile origin

    const float ix = 1.0f / dx[2 * b + 0];
    const float iy = 1.0f / dx[2 * b + 1];
    const float sx = ix * ix;                       // H-direction (d=0) scale
    const float sy = iy * iy;                       // W-direction (d=1) scale
    const float dinv = 1.0f / (-2.5f * (sx + sy));  // diag = -5/2 per dim
    const float c1 = 4.0f / 3.0f;
    const float c2 = -1.0f / 12.0f;

    const float* gb = g0  + (size_t)b * HH * WW;
    const float* rb = rhs + (size_t)b * HH * WW;
    float*       ob = out + (size_t)b * HH * WW;

    const int tid = threadIdx.x;
    const int tx  = tid & 63;       // 0..63
    const int ty  = tid >> 6;       // 0..3

    // ---- load g halo: local (li,lj) <-> global (ti+li-RAD, tj+lj-RAD) ----
    for (int li = ty; li < L; li += 4) {
        const int gi = ti + li - RAD;
        const bool vr = (unsigned)gi < (unsigned)HH;
        const float* grow = gb + (size_t)gi * WW;
        #pragma unroll
        for (int lj = tx; lj < L; lj += 64) {
            const int gj = tj + lj - RAD;
            float v = 0.0f;
            if (vr && (unsigned)gj < (unsigned)WW) v = grow[gj];
            A[li * LP + lj] = v;
        }
    }
    // ---- load rhs: local (li,lj) <-> global (ti+li-8, tj+lj-8) ----
    for (int li = ty; li < LR; li += 4) {
        const int gi = ti + li - 8;
        const bool vr = (unsigned)gi < (unsigned)HH;
        const float* rrow = rb + (size_t)gi * WW;
        #pragma unroll
        for (int lj = tx; lj < LR; lj += 64) {
            const int gj = tj + lj - 8;
            float v = 0.0f;
            if (vr && (unsigned)gj < (unsigned)WW) v = rrow[gj];
            R[li * LRP + lj] = v;
        }
    }
    __syncthreads();

    // ---- 5 fused Jacobi sweeps, shrinking valid region [lo, hi) ----
    #pragma unroll
    for (int k = 0; k < NIT; ++k) {
        float* cur = (k & 1) ? Bf : A;
        float* nxt = (k & 1) ? A  : Bf;
        const int lo = 2 + 2 * k;
        const int hi = L - 2 - 2 * k;
        for (int li = lo + ty; li < hi; li += 4) {
            const int gi = ti + li - RAD;
            const bool irow = (gi >= 2) && (gi < HH - 2);
            const float* rm2 = cur + (li - 2) * LP;
            const float* rm1 = cur + (li - 1) * LP;
            const float* r0  = cur + li * LP;
            const float* rp1 = cur + (li + 1) * LP;
            const float* rp2 = cur + (li + 2) * LP;
            const float* rr  = R + (li - 2) * LRP - 2;   // rr[lj] = R[li-2][lj-2]
            float* nx = nxt + li * LP;
            for (int lj = lo + tx; lj < hi; lj += 64) {
                const int gj = tj + lj - RAD;
                const float old  = r0[lj];
                const float vert = c2 * (rm2[lj] + rp2[lj]) + c1 * (rm1[lj] + rp1[lj]);
                const float horz = c2 * (r0[lj - 2] + r0[lj + 2]) + c1 * (r0[lj - 1] + r0[lj + 1]);
                const float conv = sx * vert + sy * horz;
                const float upd  = dinv * (rr[lj] - conv);
                const bool interior = irow && (gj >= 2) && (gj < WW - 2);
                nx[lj] = interior ? upd : old;
            }
        }
        __syncthreads();
    }

    // ---- result is in Bf (5 sweeps: A->B->A->B->A->B); store tile ----
    for (int li = RAD + ty; li < RAD + T; li += 4) {
        const int gi = ti + li - RAD;
        float* orow = ob + (size_t)gi * WW + tj;
        const float* src = Bf + li * LP + RAD;
        #pragma unroll
        for (int lj = tx; lj < T; lj += 64) {
            orow[lj] = src[lj];
        }
    }
}

extern "C" void kernel_launch(void* const* d_in, const int* in_sizes, int n_in,
                              void* d_out, int out_size) {
    const float* g0  = (const float*)d_in[0];
    const float* rhs = (const float*)d_in[1];
    const float* dx  = (const float*)d_in[2];
    float* out = (float*)d_out;

    // >48KB static smem is illegal; dynamic smem needs opt-in (capture-safe,
    // not a stream op, idempotent each call).
    cudaFuncSetAttribute(jacobi5_fused,
                         cudaFuncAttributeMaxDynamicSharedMemorySize, SMEM_BYTES);

    dim3 grid(WW / T, HH / T, NB);   // 16 x 16 x 16
    jacobi5_fused<<<grid, 256, SMEM_BYTES>>>(g0, rhs, dx, out);
}

// round 2
// speedup vs baseline: 1.0094x; 1.0094x over previous
#include <cuda_runtime.h>

// Jacobi 5-iteration temporally-blocked stencil, sm_103a.
// B=16, H=W=1024, cross stencil radius 2, boundary ring (width 2) frozen.

constexpr int HH  = 1024;
constexpr int WW  = 1024;
constexpr int NB  = 16;
constexpr int NIT = 5;
constexpr int T   = 64;             // output tile
constexpr int RAD = 2 * NIT;        // 10 halo
constexpr int L   = T + 2 * RAD;    // 84 local g extent
constexpr int LP  = L + 1;          // 85 padded stride (odd -> conflict free)
constexpr int LR  = T + 2 * (NIT - 1) * 2 - 0; // rhs extent = T+16 = 80
constexpr int LRP = LR + 1;         // 81
constexpr int SMEM_BYTES = (2 * L * LP + LR * LRP) * 4;  // 83,040 B

__global__ void __launch_bounds__(256, 2)
jacobi5_fused(const float* __restrict__ g0,
              const float* __restrict__ rhs,
              const float* __restrict__ dx,
              float* __restrict__ out)
{
    extern __shared__ float sm[];
    float* A  = sm;                 // g buffer 0: L x LP
    float* Bf = sm + L * LP;        // g buffer 1: L x LP
    float* R  = sm + 2 * L * LP;    // rhs: LR x LRP

    const int b  = blockIdx.z;
    const int ti = blockIdx.y * T;  // global row of tile origin
    const int tj = blockIdx.x * T;  // global col of tile origin

    const float ix = 1.0f / dx[2 * b + 0];
    const float iy = 1.0f / dx[2 * b + 1];
    const float sx = ix * ix;                       // H-direction (d=0) scale
    const float sy = iy * iy;                       // W-direction (d=1) scale
    const float dinv = 1.0f / (-2.5f * (sx + sy));  // diag = -5/2 per dim
    const float c1 = 4.0f / 3.0f;
    const float c2 = -1.0f / 12.0f;

    const float* gb = g0  + (size_t)b * HH * WW;
    const float* rb = rhs + (size_t)b * HH * WW;
    float*       ob = out + (size_t)b * HH * WW;

    const int tid = threadIdx.x;
    const int tx  = tid & 63;       // 0..63
    const int ty  = tid >> 6;       // 0..3

    // ---- load g halo: local (li,lj) <-> global (ti+li-RAD, tj+lj-RAD) ----
    for (int li = ty; li < L; li += 4) {
        const int gi = ti + li - RAD;
        const bool vr = (unsigned)gi < (unsigned)HH;
        const float* grow = gb + (size_t)gi * WW;
        #pragma unroll
        for (int lj = tx; lj < L; lj += 64) {
            const int gj = tj + lj - RAD;
            float v = 0.0f;
            if (vr && (unsigned)gj < (unsigned)WW) v = grow[gj];
            A[li * LP + lj] = v;
        }
    }
    // ---- load rhs: local (li,lj) <-> global (ti+li-8, tj+lj-8) ----
    for (int li = ty; li < LR; li += 4) {
        const int gi = ti + li - 8;
        const bool vr = (unsigned)gi < (unsigned)HH;
        const float* rrow = rb + (size_t)gi * WW;
        #pragma unroll
        for (int lj = tx; lj < LR; lj += 64) {
            const int gj = tj + lj - 8;
            float v = 0.0f;
            if (vr && (unsigned)gj < (unsigned)WW) v = rrow[gj];
            R[li * LRP + lj] = v;
        }
    }
    __syncthreads();

    // ---- 5 fused Jacobi sweeps, shrinking valid region [lo, hi) ----
    #pragma unroll
    for (int k = 0; k < NIT; ++k) {
        float* cur = (k & 1) ? Bf : A;
        float* nxt = (k & 1) ? A  : Bf;
        const int lo = 2 + 2 * k;
        const int hi = L - 2 - 2 * k;
        for (int li = lo + ty; li < hi; li += 4) {
            const int gi = ti + li - RAD;
            const bool irow = (gi >= 2) && (gi < HH - 2);
            const float* rm2 = cur + (li - 2) * LP;
            const float* rm1 = cur + (li - 1) * LP;
            const float* r0  = cur + li * LP;
            const float* rp1 = cur + (li + 1) * LP;
            const float* rp2 = cur + (li + 2) * LP;
            const float* rr  = R + (li - 2) * LRP - 2;   // rr[lj] = R[li-2][lj-2]
            float* nx = nxt + li * LP;
            for (int lj = lo + tx; lj < hi; lj += 64) {
                const int gj = tj + lj - RAD;
                const float old  = r0[lj];
                const float vert = c2 * (rm2[lj] + rp2[lj]) + c1 * (rm1[lj] + rp1[lj]);
                const float horz = c2 * (r0[lj - 2] + r0[lj + 2]) + c1 * (r0[lj - 1] + r0[lj + 1]);
                const float conv = sx * vert + sy * horz;
                const float upd  = dinv * (rr[lj] - conv);
                const bool interior = irow && (gj >= 2) && (gj < WW - 2);
                nx[lj] = interior ? upd : old;
            }
        }
        __syncthreads();
    }

    // ---- result is in Bf (5 sweeps: A->B->A->B->A->B); store tile ----
    for (int li = RAD + ty; li < RAD + T; li += 4) {
        const int gi = ti + li - RAD;
        float* orow = ob + (size_t)gi * WW + tj;
        const float* src = Bf + li * LP + RAD;
        #pragma unroll
        for (int lj = tx; lj < T; lj += 64) {
            orow[lj] = src[lj];
        }
    }
}

extern "C" void kernel_launch(void* const* d_in, const int* in_sizes, int n_in,
                              void* d_out, int out_size) {
    const float* g0  = (const float*)d_in[0];
    const float* rhs = (const float*)d_in[1];
    const float* dx  = (const float*)d_in[2];
    float* out = (float*)d_out;

    // >48KB static smem is illegal; dynamic smem needs opt-in (capture-safe,
    // not a stream op, idempotent each call).
    cudaFuncSetAttribute(jacobi5_fused,
                         cudaFuncAttributeMaxDynamicSharedMemorySize, SMEM_BYTES);

    dim3 grid(WW / T, HH / T, NB);   // 16 x 16 x 16
    jacobi5_fused<<<grid, 256, SMEM_BYTES>>>(g0, rhs, dx, out);
}

// round 3
// speedup vs baseline: 1.7416x; 1.7253x over previous
#include <cuda_runtime.h>

// Jacobi 5-iteration temporally-blocked cross stencil, sm_103a.
// B=16, H=W=1024, radius-2 cross, boundary ring (width 2) frozen.

constexpr int HH  = 1024;
constexpr int WW  = 1024;
constexpr int NB  = 16;
constexpr int NIT = 5;
constexpr int T   = 64;             // output tile
constexpr int RAD = 2 * NIT;        // 10 halo
constexpr int L   = T + 2 * RAD;    // 84 local g extent
constexpr int LP  = L + 1;          // 85 padded stride
constexpr int LR  = T + 16;         // 80 rhs extent
constexpr int LRP = LR + 1;         // 81
constexpr int NT  = 512;            // threads per CTA
constexpr int SMEM_BYTES = (2 * L * LP + LR * LRP) * 4;  // 83,040 B

// One Jacobi sweep over the shrinking valid region [lo, L-lo) x [lo, L-lo).
// cur/nxt are L x LP smem buffers; R is dinv-prescaled rhs (LR x LRP).
template<int K, bool EDGE>
__device__ __forceinline__ void sweep(const float* __restrict__ cur,
                                      float* __restrict__ nxt,
                                      const float* __restrict__ R,
                                      int tid, int ti, int tj,
                                      float k1x, float k2x, float k1y, float k2y)
{
    constexpr int lo    = 2 + 2 * K;
    constexpr int w     = L - 4 - 4 * K;   // 80,76,72,68
    constexpr int total = w * w;
    #pragma unroll 4
    for (int idx = tid; idx < total; idx += NT) {
        const int li = lo + idx / w;       // div by compile-time constant
        const int lj = lo + idx % w;
        const float* r0 = cur + li * LP;
        const float vert = k2x * (cur[(li - 2) * LP + lj] + cur[(li + 2) * LP + lj])
                         + k1x * (cur[(li - 1) * LP + lj] + cur[(li + 1) * LP + lj]);
        const float horz = k2y * (r0[lj - 2] + r0[lj + 2])
                         + k1y * (r0[lj - 1] + r0[lj + 1]);
        float upd = R[(li - 2) * LRP + (lj - 2)] - (vert + horz);
        if (EDGE) {
            const int gi = ti + li - RAD;
            const int gj = tj + lj - RAD;
            const bool interior = ((unsigned)(gi - 2) < (unsigned)(HH - 4)) &&
                                  ((unsigned)(gj - 2) < (unsigned)(WW - 4));
            upd = interior ? upd : r0[lj];
        }
        nxt[li * LP + lj] = upd;
    }
}

// Final sweep (K=4): write results directly to global memory.
template<bool EDGE>
__device__ __forceinline__ void sweep_last(const float* __restrict__ cur,
                                           const float* __restrict__ R,
                                           float* __restrict__ ob,
                                           int tid, int ti, int tj,
                                           float k1x, float k2x, float k1y, float k2y)
{
    #pragma unroll 4
    for (int idx = tid; idx < T * T; idx += NT) {
        const int li = RAD + (idx >> 6);
        const int lj = RAD + (idx & 63);
        const float* r0 = cur + li * LP;
        const float vert = k2x * (cur[(li - 2) * LP + lj] + cur[(li + 2) * LP + lj])
                         + k1x * (cur[(li - 1) * LP + lj] + cur[(li + 1) * LP + lj]);
        const float horz = k2y * (r0[lj - 2] + r0[lj + 2])
                         + k1y * (r0[lj - 1] + r0[lj + 1]);
        float upd = R[(li - 2) * LRP + (lj - 2)] - (vert + horz);
        const int gi = ti + li - RAD;
        const int gj = tj + lj - RAD;
        if (EDGE) {
            const bool interior = ((unsigned)(gi - 2) < (unsigned)(HH - 4)) &&
                                  ((unsigned)(gj - 2) < (unsigned)(WW - 4));
            upd = interior ? upd : r0[lj];
        }
        ob[(size_t)gi * WW + gj] = upd;    // consecutive tid -> consecutive gj
    }
}

template<bool EDGE>
__device__ __forceinline__ void run_sweeps(float* A, float* Bf, const float* R,
                                           float* ob, int tid, int ti, int tj,
                                           float k1x, float k2x, float k1y, float k2y)
{
    sweep<0, EDGE>(A,  Bf, R, tid, ti, tj, k1x, k2x, k1y, k2y);
    __syncthreads();
    sweep<1, EDGE>(Bf, A,  R, tid, ti, tj, k1x, k2x, k1y, k2y);
    __syncthreads();
    sweep<2, EDGE>(A,  Bf, R, tid, ti, tj, k1x, k2x, k1y, k2y);
    __syncthreads();
    sweep<3, EDGE>(Bf, A,  R, tid, ti, tj, k1x, k2x, k1y, k2y);
    __syncthreads();
    sweep_last<EDGE>(A, R, ob, tid, ti, tj, k1x, k2x, k1y, k2y);
}

__global__ void __launch_bounds__(NT, 2)
jacobi5_fused(const float* __restrict__ g0,
              const float* __restrict__ rhs,
              const float* __restrict__ dx,
              float* __restrict__ out)
{
    extern __shared__ float sm[];
    float* A  = sm;                 // g buffer 0: L x LP
    float* Bf = sm + L * LP;        // g buffer 1: L x LP
    float* R  = sm + 2 * L * LP;    // dinv-prescaled rhs: LR x LRP

    const int b  = blockIdx.z;
    const int ti = blockIdx.y * T;
    const int tj = blockIdx.x * T;

    const float ix = 1.0f / dx[2 * b + 0];
    const float iy = 1.0f / dx[2 * b + 1];
    const float sx = ix * ix;
    const float sy = iy * iy;
    const float dinv = 1.0f / (-2.5f * (sx + sy));
    const float k1x = dinv * sx * (4.0f / 3.0f);
    const float k2x = dinv * sx * (-1.0f / 12.0f);
    const float k1y = dinv * sy * (4.0f / 3.0f);
    const float k2y = dinv * sy * (-1.0f / 12.0f);

    const float* gb = g0  + (size_t)b * HH * WW;
    const float* rb = rhs + (size_t)b * HH * WW;
    float*       ob = out + (size_t)b * HH * WW;

    const int tid = threadIdx.x;

    // ---- load g halo (flat): local (li,lj) <-> global (ti+li-RAD, tj+lj-RAD) ----
    for (int idx = tid; idx < L * L; idx += NT) {
        const int li = idx / L;
        const int lj = idx % L;
        const int gi = ti + li - RAD;
        const int gj = tj + lj - RAD;
        float v = 0.0f;
        if (((unsigned)gi < (unsigned)HH) && ((unsigned)gj < (unsigned)WW))
            v = gb[(size_t)gi * WW + gj];
        A[li * LP + lj] = v;
    }
    // ---- load rhs prescaled by dinv: local (li,lj) <-> global (ti+li-8, tj+lj-8) ----
    for (int idx = tid; idx < LR * LR; idx += NT) {
        const int li = idx / LR;
        const int lj = idx % LR;
        const int gi = ti + li - 8;
        const int gj = tj + lj - 8;
        float v = 0.0f;
        if (((unsigned)gi < (unsigned)HH) && ((unsigned)gj < (unsigned)WW))
            v = rb[(size_t)gi * WW + gj];
        R[li * LRP + lj] = dinv * v;
    }
    __syncthreads();

    const bool edge = (blockIdx.x == 0) | (blockIdx.x == gridDim.x - 1) |
                      (blockIdx.y == 0) | (blockIdx.y == gridDim.y - 1);
    if (edge)
        run_sweeps<true >(A, Bf, R, ob, tid, ti, tj, k1x, k2x, k1y, k2y);
    else
        run_sweeps<false>(A, Bf, R, ob, tid, ti, tj, k1x, k2x, k1y, k2y);
}

extern "C" void kernel_launch(void* const* d_in, const int* in_sizes, int n_in,
                              void* d_out, int out_size) {
    const float* g0  = (const float*)d_in[0];
    const float* rhs = (const float*)d_in[1];
    const float* dx  = (const float*)d_in[2];
    float* out = (float*)d_out;

    cudaFuncSetAttribute(jacobi5_fused,
                         cudaFuncAttributeMaxDynamicSharedMemorySize, SMEM_BYTES);

    dim3 grid(WW / T, HH / T, NB);   // 16 x 16 x 16
    jacobi5_fused<<<grid, NT, SMEM_BYTES>>>(g0, rhs, dx, out);
}